// round 16
// baseline (speedup 1.0000x reference)
#include <cuda_runtime.h>

#define BATCH 4
#define NV 4096
#define NM 8192
#define BIGF 1e10f

#define NSTRIP 16              // m-strips per batch
#define STRIPM (NM / NSTRIP)   // 512
#define BM     256             // p-cols per tile
#define NTILE  (STRIPM / BM)   // 2
#define NVB    (NV / 128)      // 32 v-row blocks

typedef unsigned long long u64;

// ------------------------ scratch (device globals, no allocs) ---------------
__device__ float g_d1p[NSTRIP][BATCH * NV];   // min over a strip's p, per v row
__device__ float g_d2p[NVB][BATCH * NM];      // min over a 128-row v block, per p col
__device__ float g_sum1[BATCH], g_sum2[BATCH], g_cnt[BATCH];
__device__ unsigned g_done;

// ------------------------ packed f32x2 helpers ------------------------------
__device__ __forceinline__ u64 pack2(float lo, float hi) {
    u64 d;
    asm("mov.b64 %0, {%1, %2};" : "=l"(d) : "f"(lo), "f"(hi));
    return d;
}
__device__ __forceinline__ u64 fma2(u64 a, u64 b, u64 c) {
    u64 d;
    asm("fma.rn.f32x2 %0, %1, %2, %3;" : "=l"(d) : "l"(a), "l"(b), "l"(c));
    return d;
}
__device__ __forceinline__ u64 add2(u64 a, u64 b) {
    u64 d;
    asm("add.rn.f32x2 %0, %1, %2;" : "=l"(d) : "l"(a), "l"(b));
    return d;
}
__device__ __forceinline__ float2 asf2(u64 v) {
    union { u64 u; float2 f; } c; c.u = v; return c.f;
}

// ------------------------ 1) fused transform + pairwise min ------------------
// Block: 128 v-rows x 512 p-cols (2 tiles of 256), 256 threads, grid=2048.
// Manual smem->reg double-buffer of p across j; split cj accumulators.
__global__ __launch_bounds__(256, 3) void chamfer_kernel(
        const float* __restrict__ vert, const float* __restrict__ pc) {
    __shared__ u64   spx[2][BM];
    __shared__ u64   spy[2][BM];
    __shared__ u64   spz[2][BM];
    __shared__ u64   spw[2][BM];
    __shared__ float sred[BM * 17];    // padded reduction scratch
    __shared__ __align__(16) float svx[128], svy[128], svz[128], scv[128];

    int b   = blockIdx.z;
    int y   = blockIdx.y;
    int n0  = y * 128;
    int s   = blockIdx.x;
    int mb0 = s * STRIPM;
    int tid = threadIdx.x;
    int ty  = tid >> 4;
    int tx  = tid & 15;

    // one block zeroes the final-stage accumulators (nobody reads them in K1)
    if (blockIdx.x == 0 && blockIdx.y == 0 && blockIdx.z == 0 && tid < BATCH) {
        g_sum1[tid] = 0.f; g_sum2[tid] = 0.f; g_cnt[tid] = 0.f;
        if (tid == 0) g_done = 0u;
    }

    // ---- transform my v rows (top surface gather) ----
    if (tid < 128) {
        int r = n0 + tid;
        int i = r >> 6, k = r & 63;
        // vertices[b, c, i, 31, k]; shape (4,3,64,32,64)
        int base = ((b * 3) * 64 + i) * 2048 + 31 * 64 + k;
        float v0 = (vert[base]          - 0.5f) * 2.f;
        float v1 = (vert[base + 131072] - 0.5f) * 2.f;
        float v2 = (vert[base + 262144] - 0.5f) * 2.f;
        svx[tid] = v0; svy[tid] = v1; svz[tid] = v2;
        scv[tid] = fmaf(v0, v0, fmaf(v1, v1, v2 * v2));
    }
    // ---- p tile 0: all 256 threads, 1 column each ----
    {
        int m = mb0 + tid;
        float p0 = pc[(b * 3 + 0) * NM + m];
        float p1 = pc[(b * 3 + 1) * NM + m];
        float p2 = pc[(b * 3 + 2) * NM + m];
        bool valid = (p0 != 0.f) || (p1 != 0.f) || (p2 != 0.f);
        float cp = valid ? fmaf(p0, p0, fmaf(p1, p1, p2 * p2)) : BIGF;
        spx[0][tid] = pack2(-2.f * p0, -2.f * p0);
        spy[0][tid] = pack2(-2.f * p1, -2.f * p1);
        spz[0][tid] = pack2(-2.f * p2, -2.f * p2);
        spw[0][tid] = pack2(cp, cp);
    }
    __syncthreads();

    // ---- my 8 v-rows as packed pairs (broadcast LDS.64 from SoA smem) ----
    u64 vx2[4], vy2[4], vz2[4], cv2[4];
#pragma unroll
    for (int q = 0; q < 4; q++) {
        int r = 8 * ty + 2 * q;
        vx2[q] = *(const u64*)&svx[r];
        vy2[q] = *(const u64*)&svy[r];
        vz2[q] = *(const u64*)&svz[r];
        cv2[q] = *(const u64*)&scv[r];
    }

    float rmin[8];
#pragma unroll
    for (int k = 0; k < 8; k++) rmin[k] = 3.4e38f;

#pragma unroll
    for (int t = 0; t < NTILE; t++) {
        int cur = t & 1, nxt = cur ^ 1;

        // p registers for column j (rotating double-buffer across j)
        u64 pxx = spx[cur][tx];
        u64 pyy = spy[cur][tx];
        u64 pzz = spz[cur][tx];
        u64 cpp = spw[cur][tx];

#pragma unroll
        for (int j = 0; j < 16; j++) {
            // prefetch column j+1 before computing j
            u64 nxx, nyy, nzz, ncp;
            if (j + 1 < 16) {
                int c = tx + 16 * (j + 1);
                nxx = spx[cur][c];
                nyy = spy[cur][c];
                nzz = spz[cur][c];
                ncp = spw[cur][c];
            }

            float cjx = 3.4e38f, cjy = 3.4e38f;
#pragma unroll
            for (int q = 0; q < 4; q++) {
                // tq = cp - 2 v.p  (both rows of the pair)
                u64 tq = fma2(vz2[q], pzz, cpp);
                tq = fma2(vy2[q], pyy, tq);
                tq = fma2(vx2[q], pxx, tq);
                float2 a = asf2(tq);
                rmin[2 * q]     = fminf(rmin[2 * q],     a.x);   // cv added at end
                rmin[2 * q + 1] = fminf(rmin[2 * q + 1], a.y);
                float2 e = asf2(add2(tq, cv2[q]));               // full d for p-side
                cjx = fminf(cjx, e.x);
                cjy = fminf(cjy, e.y);
            }
            sred[(tx + 16 * j) * 17 + ty] = fminf(cjx, cjy);  // conflict-free

            pxx = nxx; pyy = nyy; pzz = nzz; cpp = ncp;
        }

        // prefetch + transform next tile AFTER compute (covered by reduce phase)
        float pnx, pny, pnz, pnw;
        if (t + 1 < NTILE) {
            int m = mb0 + (t + 1) * BM + tid;
            float p0 = pc[(b * 3 + 0) * NM + m];
            float p1 = pc[(b * 3 + 1) * NM + m];
            float p2 = pc[(b * 3 + 2) * NM + m];
            bool valid = (p0 != 0.f) || (p1 != 0.f) || (p2 != 0.f);
            pnw = valid ? fmaf(p0, p0, fmaf(p1, p1, p2 * p2)) : BIGF;
            pnx = -2.f * p0; pny = -2.f * p1; pnz = -2.f * p2;
        }
        __syncthreads();

        // commit prefetched tile (buffer nxt was last read in tile t-1)
        if (t + 1 < NTILE) {
            spx[nxt][tid] = pack2(pnx, pnx);
            spy[nxt][tid] = pack2(pny, pny);
            spz[nxt][tid] = pack2(pnz, pnz);
            spw[nxt][tid] = pack2(pnw, pnw);
        }

        // ---- dist2: every thread reduces one of the 256 columns ----
        {
            float mn = sred[tid * 17];
#pragma unroll
            for (int k = 1; k < 16; k++) mn = fminf(mn, sred[tid * 17 + k]);
            g_d2p[y][b * NM + mb0 + t * BM + tid] = mn;   // coalesced store
        }
        __syncthreads();
    }

    // ---- dist1 partial: once per block ----
#pragma unroll
    for (int k = 0; k < 8; k++)
        sred[(8 * ty + k) * 17 + tx] = rmin[k];
    __syncthreads();
    if (tid < 128) {
        float mn = sred[tid * 17];
#pragma unroll
        for (int k = 1; k < 16; k++) mn = fminf(mn, sred[tid * 17 + k]);
        g_d1p[s][b * NV + n0 + tid] = mn + scv[tid];      // coalesced store
    }
}

// ------------------------ 2) final reduction --------------------------------
// 256 blocks (64 per batch), 256 threads; parallel across the reduction dim.
// Mask via sentinel: invalid p-cols carry mins >= 1e10 (cp=BIGF), no pc reads.
__global__ void final_kernel(float* __restrict__ out) {
    __shared__ float4 p2[256];    // d2 stage-1 partials
    __shared__ float2 p1[256];    // d1 stage-1 partials
    __shared__ float sh[4];
    __shared__ bool last;
    int tid  = threadIdx.x;
    int b    = blockIdx.x >> 6;
    int part = blockIdx.x & 63;

    // ---- d2 stage 1: block covers 128 m-cols = 32 quads; 8 yy-groups of 4 ----
    {
        int q  = tid & 31;          // m-quad
        int yg = tid >> 5;          // yy-group (0..7)
        int m  = part * 128 + q * 4;
        float4 mn = make_float4(3.4e38f, 3.4e38f, 3.4e38f, 3.4e38f);
#pragma unroll
        for (int k = 0; k < 4; k++) {
            float4 v = *(const float4*)&g_d2p[yg * 4 + k][b * NM + m];
            mn.x = fminf(mn.x, v.x); mn.y = fminf(mn.y, v.y);
            mn.z = fminf(mn.z, v.z); mn.w = fminf(mn.w, v.w);
        }
        p2[tid] = mn;
    }
    // ---- d1 stage 1: block covers 64 v-rows = 32 pairs; 8 groups x 2 strips --
    {
        int pr = tid & 31;          // n-pair
        int sg = tid >> 5;          // strip-group (0..7) -> strips 2sg, 2sg+1
        int n  = part * 64 + pr * 2;
        float2 a = *(const float2*)&g_d1p[2 * sg][b * NV + n];
        float2 c = *(const float2*)&g_d1p[2 * sg + 1][b * NV + n];
        p1[tid] = make_float2(fminf(a.x, c.x), fminf(a.y, c.y));
    }
    __syncthreads();

    // ---- stage 2 + sentinel-masked accumulate ----
    float s1 = 0.f, s2 = 0.f, c2 = 0.f;
    if (tid < 32) {
        float4 mn = p2[tid];
#pragma unroll
        for (int k = 1; k < 8; k++) {
            float4 v = p2[tid + 32 * k];
            mn.x = fminf(mn.x, v.x); mn.y = fminf(mn.y, v.y);
            mn.z = fminf(mn.z, v.z); mn.w = fminf(mn.w, v.w);
        }
        if (mn.x < 1e9f) { s2 += mn.x; c2 += 1.f; }
        if (mn.y < 1e9f) { s2 += mn.y; c2 += 1.f; }
        if (mn.z < 1e9f) { s2 += mn.z; c2 += 1.f; }
        if (mn.w < 1e9f) { s2 += mn.w; c2 += 1.f; }
    } else if (tid < 64) {
        int pr = tid - 32;
        float2 mn = p1[pr];
#pragma unroll
        for (int k = 1; k < 8; k++) {
            float2 v = p1[pr + 32 * k];
            mn.x = fminf(mn.x, v.x); mn.y = fminf(mn.y, v.y);
        }
        s1 = mn.x + mn.y;
    }

#pragma unroll
    for (int o = 16; o > 0; o >>= 1) {
        s1 += __shfl_down_sync(0xffffffffu, s1, o);
        s2 += __shfl_down_sync(0xffffffffu, s2, o);
        c2 += __shfl_down_sync(0xffffffffu, c2, o);
    }
    if (tid == 0)  { sh[0] = s2; sh[1] = c2; }
    if (tid == 32) { sh[2] = s1; }
    __syncthreads();

    if (tid == 0) {
        atomicAdd(&g_sum1[b], sh[2]);
        atomicAdd(&g_sum2[b], sh[0]);
        atomicAdd(&g_cnt[b],  sh[1]);
        __threadfence();
        unsigned done = atomicAdd(&g_done, 1u);
        last = (done == gridDim.x - 1);
    }
    __syncthreads();

    if (last && tid == 0) {
        float acc = 0.f;
        for (int bb = 0; bb < BATCH; bb++)
            acc += g_sum1[bb] / (float)NV + g_sum2[bb] / fmaxf(g_cnt[bb], 1.f);
        out[0] = acc / (float)BATCH;
    }
}

// ------------------------ launch --------------------------------------------
extern "C" void kernel_launch(void* const* d_in, const int* in_sizes, int n_in,
                              void* d_out, int out_size) {
    const float* vert = (const float*)d_in[0];
    const float* pc   = (const float*)d_in[1];
    if (in_sizes[0] == BATCH * 3 * NM) {   // defensive input identification
        vert = (const float*)d_in[1];
        pc   = (const float*)d_in[0];
    }

    dim3 grid(NSTRIP, NVB, BATCH);
    chamfer_kernel<<<grid, 256>>>(vert, pc);
    final_kernel<<<256, 256>>>((float*)d_out);
}